// round 14
// baseline (speedup 1.0000x reference)
#include <cuda_runtime.h>
#include <cstdint>
#include <math.h>

#define T_LEN 2048
#define BSZ   32
#define DIM   256
#define HID   256
#define LAY   2

typedef unsigned long long ull;

// Scratch: gx[t][l][gate3][b][h]  (2048*2*3*32*256 floats = 402MB)
__device__ float g_gx[(size_t)T_LEN * LAY * 3 * BSZ * HID];

__device__ __forceinline__ void ffma2(ull& d, ull a, ull b) {
    asm("fma.rn.f32x2 %0, %1, %2, %0;" : "+l"(d) : "l"(a), "l"(b));
}
__device__ __forceinline__ float2 unpack2(ull v) {
    float2 r; asm("mov.b64 {%0, %1}, %2;" : "=f"(r.x), "=f"(r.y) : "l"(v)); return r;
}
__device__ __forceinline__ float hsum2(ull v) {
    float2 r = unpack2(v); return r.x + r.y;
}
__device__ __forceinline__ void cp_async16(uint32_t sdst, const void* gsrc) {
    asm volatile("cp.async.ca.shared.global [%0], [%1], 16;" :: "r"(sdst), "l"(gsrc));
}

// ---------------------------------------------------------------------------
// Kernel 1: gx GEMM. 64m x 128n CTA tile, 128 threads, 8x8 thread tile,
// cp.async double-buffered, 2 CTAs/SM.  (R13 config, ~1.15 ms)
// ---------------------------------------------------------------------------
#define GPAD 68
#define A_F  (64 * GPAD)
#define B_F  (128 * GPAD)
#define ST_F (A_F + B_F)

__global__ __launch_bounds__(128, 2)
void gx_gemm_kernel(const float* __restrict__ x, const float* __restrict__ Wx,
                    const float* __restrict__ bx)
{
    extern __shared__ float sm1[];
    const int tid = threadIdx.x;
    const int tx  = tid & 15;
    const int ty  = tid >> 4;
    const int nbase = blockIdx.x * 128;
    const int mbase = blockIdx.y * 64;

    const uint32_t sm_u = (uint32_t)__cvta_generic_to_shared(sm1);

    auto issue = [&](int stage, int kofs) {
        const uint32_t sb = sm_u + (uint32_t)(stage * ST_F * 4);
        for (int idx = tid; idx < 64 * 16; idx += 128) {
            int r = idx >> 4, q = idx & 15;
            cp_async16(sb + (uint32_t)((r * GPAD + (q << 2)) * 4),
                       x + (((size_t)(mbase + r)) << 8) + kofs + (q << 2));
        }
        for (int idx = tid; idx < 128 * 16; idx += 128) {
            int r = idx >> 4, q = idx & 15;
            cp_async16(sb + (uint32_t)((A_F + r * GPAD + (q << 2)) * 4),
                       Wx + (((size_t)(nbase + r)) << 8) + kofs + (q << 2));
        }
        asm volatile("cp.async.commit_group;");
    };

    int   ncol[8];
    float bias[8];
#pragma unroll
    for (int jj = 0; jj < 8; jj++) {
        ncol[jj] = nbase + tx + 16 * jj;
        bias[jj] = bx[ncol[jj]];
    }

    ull acc2[8][8];
#pragma unroll
    for (int i = 0; i < 8; i++)
#pragma unroll
        for (int j = 0; j < 8; j++) acc2[i][j] = 0ull;

    issue(0, 0);

    for (int kc = 0; kc < 4; kc++) {
        if (kc < 3) {
            issue((kc + 1) & 1, (kc + 1) * 64);
            asm volatile("cp.async.wait_group 1;");
        } else {
            asm volatile("cp.async.wait_group 0;");
        }
        __syncthreads();

        const float* cA = sm1 + (kc & 1) * ST_F;
        const float* cB = cA + A_F;
#pragma unroll 2
        for (int q = 0; q < 16; q++) {
            ulonglong2 av[8], bv[8];
#pragma unroll
            for (int i = 0; i < 8; i++)
                av[i] = *reinterpret_cast<const ulonglong2*>(cA + (ty * 8 + i) * GPAD + (q << 2));
#pragma unroll
            for (int j = 0; j < 8; j++)
                bv[j] = *reinterpret_cast<const ulonglong2*>(cB + (tx + 16 * j) * GPAD + (q << 2));
#pragma unroll
            for (int i = 0; i < 8; i++)
#pragma unroll
                for (int j = 0; j < 8; j++) {
                    ffma2(acc2[i][j], av[i].x, bv[j].x);
                    ffma2(acc2[i][j], av[i].y, bv[j].y);
                }
        }
        __syncthreads();
    }

#pragma unroll
    for (int jj = 0; jj < 8; jj++) {
        const int n  = ncol[jj];
        const int l  = n / 768;
        const int rr = n - l * 768;
        const int g3 = rr >> 8;
        const int h  = rr & 255;
#pragma unroll
        for (int ii = 0; ii < 8; ii++) {
            const int m = mbase + ty * 8 + ii;
            const int b = m >> 11;
            const int t = m & 2047;
            const size_t o =
                ((((size_t)t * LAY + l) * 3 + g3) * BSZ + b) * HID + h;
            g_gx[o] = hsum2(acc2[ii][jj]) + bias[jj];
        }
    }
}

// ---------------------------------------------------------------------------
// Kernel 2: cluster-persistent FUSED-BIDIRECTIONAL GRU scan.
// 128 CTAs = 2 layers x 16 batch-chunks(2 batches) x 4-CTA cluster, 256 thr.
// One super-step covers fwd AND bwd (same Wh!): one fused 12-acc dot
// (h-streams F·b0,F·b1,B·b0,B·b1 — byte-identical to R8's proven loop),
// ONE __syncthreads, ONE parallel 256-thread combine (each thread owns
// (dir,batch,h)), ONE cluster arrive/wait. Halves overhead per unit work.
// ---------------------------------------------------------------------------
#define SC_THREADS 256
#define PADK    260
#define SW3_F   (2 * 32 * PADK)      // 16640 floats
#define PART_F  (4 * 4 * 192)        // 4 planes (dir,b) x [4kc][192rr] scalars
#define HB1_F   (2 * 2 * 256)        // per direction: [2p][2b][256k]

__device__ __forceinline__ void st_cluster_f32(uint32_t saddr, int trank, float v)
{
    uint32_t ra;
    asm volatile("mapa.shared::cluster.u32 %0, %1, %2;" : "=r"(ra) : "r"(saddr), "r"(trank));
    asm volatile("st.shared::cluster.f32 [%0], %1;" :: "r"(ra), "f"(v) : "memory");
}
__device__ __forceinline__ void cluster_arrive()
{ asm volatile("barrier.cluster.arrive.aligned;" ::: "memory"); }
__device__ __forceinline__ void cluster_wait()
{ asm volatile("barrier.cluster.wait.aligned;" ::: "memory"); }
__device__ __forceinline__ float sig_fast(float x) {
    return __fdividef(1.f, 1.f + __expf(-x));
}
__device__ __forceinline__ float tanh_fast(float x) {
    x = fminf(fmaxf(x, -15.f), 15.f);
    float e = __expf(2.f * x);
    return __fdividef(e - 1.f, e + 1.f);
}

__global__ void __cluster_dims__(4, 1, 1) __launch_bounds__(SC_THREADS, 1)
gru_scan_kernel(const float* __restrict__ Wh, const float* __restrict__ bh,
                float* __restrict__ out)
{
    extern __shared__ float sm[];
    float* sw3   = sm;                  // [64 rows][PADK]  (row2 weights)
    float* part  = sw3 + SW3_F;         // [4 db][4 kc][192 rr] scalars
    float* hbufF = part + PART_F;       // [2 p][2 b][256 k]
    float* hbufB = hbufF + HB1_F;       // [2 p][2 b][256 k]

    const int tid  = threadIdx.x;
    const int lane = tid & 31;
    const int wid  = tid >> 5;
    const int rg   = wid >> 2;          // row group (96 rows)
    const int kc   = wid & 3;           // k-chunk
    const int k0   = kc << 6;

    const int rank = blockIdx.x & 3;
    const int cg   = blockIdx.x >> 2;   // 0..31
    const int l    = cg >> 4;           // layer
    const int c    = cg & 15;           // batch chunk
    const int b0   = c * 2;

    // combine identity: 256 threads, each owns (dir, batch, h)
    const int dirT = tid >> 7;          // 0 = fwd, 1 = bwd
    const int bbT  = (tid >> 6) & 1;
    const int liT  = tid & 63;
    const int hiT  = rank * 64 + liT;

    const float* WhL = Wh + (size_t)l * 768 * 256;

    // 2 register weight rows as packed k-pairs (static indexing only)
    const int rrA = rg * 96 + lane * 3;
    ull w0r[32], w1r[32];
    {
        int r0 = rrA + 0, r1 = rrA + 1;
        const ull* p0 = reinterpret_cast<const ull*>(
            WhL + (size_t)((r0 >> 6) * 256 + rank * 64 + (r0 & 63)) * 256 + k0);
        const ull* p1 = reinterpret_cast<const ull*>(
            WhL + (size_t)((r1 >> 6) * 256 + rank * 64 + (r1 & 63)) * 256 + k0);
#pragma unroll
        for (int q = 0; q < 32; q++) { w0r[q] = p0[q]; w1r[q] = p1[q]; }
    }

    // 3rd-row smem plane: sw3[(rg*32+lane)][k]
    for (int i = tid; i < 2 * 32 * 256; i += SC_THREADS) {
        int ri = i >> 8;
        int k  = i & 255;
        int rg_ = ri >> 5;
        int ln  = ri & 31;
        int rr  = rg_ * 96 + ln * 3 + 2;
        sw3[ri * PADK + k] = WhL[(size_t)((rr >> 6) * 256 + rank * 64 + (rr & 63)) * 256 + k];
    }
    for (int i = tid; i < 2 * HB1_F; i += SC_THREADS) hbufF[i] = 0.f;  // covers hbufB

    const float br = bh[l * 768 +       hiT];
    const float bz = bh[l * 768 + 256 + hiT];
    const float bn = bh[l * 768 + 512 + hiT];

    __syncthreads();
    cluster_arrive(); cluster_wait();   // init visible cluster-wide
    cluster_arrive();                   // pre-arm for iter-0 wait

    const uint32_t hbF_saddr = (uint32_t)__cvta_generic_to_shared(hbufF);
    const uint32_t hbB_saddr = (uint32_t)__cvta_generic_to_shared(hbufB);
    const size_t gsz = (size_t)BSZ * HID;
    const size_t obstride = (size_t)T_LEN * LAY * 2 * HID;

    float hprev = 0.f;
    int p = 0;

    for (int step = 0; step < T_LEN; step++) {
        const int tT = dirT ? (T_LEN - 1 - step) : step;   // this thread's time

        // gx prefetch for combine (own dir/batch/h) — in flight over the wait
        float gxr, gxz, gxn;
        {
            const size_t base = ((size_t)tT * LAY + l) * 3 * gsz
                              + (size_t)(b0 + bbT) * HID + hiT;
            gxr = __ldg(g_gx + base);
            gxz = __ldg(g_gx + base + gsz);
            gxn = __ldg(g_gx + base + 2 * gsz);
        }

        cluster_wait();   // h_F(p), h_B(p) visible cluster-wide

        // --- fused dot: 3 rows x {F.b0,F.b1,B.b0,B.b1} over 64 k ---
        ull a00 = 0, a01 = 0, a02 = 0, a03 = 0;
        ull a10 = 0, a11 = 0, a12 = 0, a13 = 0;
        ull a20 = 0, a21 = 0, a22 = 0, a23 = 0;
        {
            const ulonglong2* h0p = reinterpret_cast<const ulonglong2*>(hbufF + p * 512 + k0);
            const ulonglong2* h1p = reinterpret_cast<const ulonglong2*>(hbufF + p * 512 + 256 + k0);
            const ulonglong2* h2p = reinterpret_cast<const ulonglong2*>(hbufB + p * 512 + k0);
            const ulonglong2* h3p = reinterpret_cast<const ulonglong2*>(hbufB + p * 512 + 256 + k0);
            const ulonglong2* w3p = reinterpret_cast<const ulonglong2*>(
                sw3 + (rg * 32 + lane) * PADK + k0);

#pragma unroll
            for (int q = 0; q < 16; q++) {
                const ulonglong2 w3 = w3p[q];
                const ulonglong2 hh0 = h0p[q];
                const ulonglong2 hh1 = h1p[q];
                const ulonglong2 hh2 = h2p[q];
                const ulonglong2 hh3 = h3p[q];
                const ull wa0 = w0r[2 * q], wa1 = w0r[2 * q + 1];
                const ull wb0 = w1r[2 * q], wb1 = w1r[2 * q + 1];
                ffma2(a00, wa0, hh0.x); ffma2(a00, wa1, hh0.y);
                ffma2(a01, wa0, hh1.x); ffma2(a01, wa1, hh1.y);
                ffma2(a02, wa0, hh2.x); ffma2(a02, wa1, hh2.y);
                ffma2(a03, wa0, hh3.x); ffma2(a03, wa1, hh3.y);
                ffma2(a10, wb0, hh0.x); ffma2(a10, wb1, hh0.y);
                ffma2(a11, wb0, hh1.x); ffma2(a11, wb1, hh1.y);
                ffma2(a12, wb0, hh2.x); ffma2(a12, wb1, hh2.y);
                ffma2(a13, wb0, hh3.x); ffma2(a13, wb1, hh3.y);
                ffma2(a20, w3.x, hh0.x); ffma2(a20, w3.y, hh0.y);
                ffma2(a21, w3.x, hh1.x); ffma2(a21, w3.y, hh1.y);
                ffma2(a22, w3.x, hh2.x); ffma2(a22, w3.y, hh2.y);
                ffma2(a23, w3.x, hh3.x); ffma2(a23, w3.y, hh3.y);
            }
        }
        // partial stores: part[db][kc][rr], db = dir*2+b. lane-stride 3 -> CF.
        {
            float* pp = part + kc * 192 + rrA;
            pp[0 * 768 + 0] = hsum2(a00); pp[0 * 768 + 1] = hsum2(a10); pp[0 * 768 + 2] = hsum2(a20);
            pp[1 * 768 + 0] = hsum2(a01); pp[1 * 768 + 1] = hsum2(a11); pp[1 * 768 + 2] = hsum2(a21);
            pp[2 * 768 + 0] = hsum2(a02); pp[2 * 768 + 1] = hsum2(a12); pp[2 * 768 + 2] = hsum2(a22);
            pp[3 * 768 + 0] = hsum2(a03); pp[3 * 768 + 1] = hsum2(a13); pp[3 * 768 + 2] = hsum2(a23);
        }
        __syncthreads();

        // --- single parallel combine: 256 threads, each (dir,batch,h) ---
        float h;
        {
            const float* pc = part + (dirT * 2 + bbT) * 768 + liT;  // [kc*192 + g*64]
            const float sR = (pc[0] + pc[192]) + (pc[384] + pc[576]);
            const float sZ = (pc[64] + pc[256]) + (pc[448] + pc[640]);
            const float sN = (pc[128] + pc[320]) + (pc[512] + pc[704]);

            const float r = sig_fast(gxr + sR + br);
            const float z = sig_fast(gxz + sZ + bz);
            const float n = tanh_fast(gxn + r * (sN + bn));
            h = (1.f - z) * n + z * hprev;
            hprev = h;

            // broadcast h to all 4 ranks' hbuf{F,B}[1-p][bb][hi]
            const uint32_t base = dirT ? hbB_saddr : hbF_saddr;
            const uint32_t la = base
                + (uint32_t)((((1 - p) * 2 + bbT) * 256 + hiT) * 4);
            st_cluster_f32(la, 0, h);
            st_cluster_f32(la, 1, h);
            st_cluster_f32(la, 2, h);
            st_cluster_f32(la, 3, h);
        }

        cluster_arrive();   // ONE release for both directions

        out[(size_t)(b0 + bbT) * obstride
            + ((size_t)tT * LAY + l) * (2 * HID) + dirT * HID + hiT] = h;

        p ^= 1;
    }
    cluster_wait();
}

// ---------------------------------------------------------------------------
extern "C" void kernel_launch(void* const* d_in, const int* in_sizes, int n_in,
                              void* d_out, int out_size)
{
    (void)in_sizes; (void)n_in; (void)out_size;
    const float* x  = (const float*)d_in[0];
    const float* Wx = (const float*)d_in[1];
    const float* Wh = (const float*)d_in[2];
    const float* bx = (const float*)d_in[3];
    const float* bh = (const float*)d_in[4];
    float* out = (float*)d_out;

    const int smem1 = 2 * ST_F * 4;                              // 104,448 B
    const int smem2 = (SW3_F + PART_F + 2 * HB1_F) * 4;          //  87,040 B

    cudaFuncSetAttribute(gx_gemm_kernel, cudaFuncAttributeMaxDynamicSharedMemorySize, smem1);
    cudaFuncSetAttribute(gru_scan_kernel, cudaFuncAttributeMaxDynamicSharedMemorySize, smem2);

    dim3 grid1(1536 / 128, 65536 / 64);   // 12 x 1024 CTAs, 128 threads each
    gx_gemm_kernel<<<grid1, 128, smem1>>>(x, Wx, bx);

    gru_scan_kernel<<<128, SC_THREADS, smem2>>>(Wh, bh, out);
}

// round 15
// speedup vs baseline: 1.1453x; 1.1453x over previous
#include <cuda_runtime.h>
#include <cstdint>
#include <math.h>

#define T_LEN 2048
#define BSZ   32
#define DIM   256
#define HID   256
#define LAY   2

typedef unsigned long long ull;

// Scratch: gx[t][l][gate3][b][h]  (2048*2*3*32*256 floats = 402MB)
__device__ float g_gx[(size_t)T_LEN * LAY * 3 * BSZ * HID];

__device__ __forceinline__ void ffma2(ull& d, ull a, ull b) {
    asm("fma.rn.f32x2 %0, %1, %2, %0;" : "+l"(d) : "l"(a), "l"(b));
}
__device__ __forceinline__ float2 unpack2(ull v) {
    float2 r; asm("mov.b64 {%0, %1}, %2;" : "=f"(r.x), "=f"(r.y) : "l"(v)); return r;
}
__device__ __forceinline__ float hsum2(ull v) {
    float2 r = unpack2(v); return r.x + r.y;
}

// ---------------------------------------------------------------------------
// Kernel 1: gx GEMM v2 — transposed k-pair-packed operands, outer product.
// CTA: 64m x 128n, 128 threads, thread = 8m (bcast) x 8n (lane-consec).
// Per kpair/thread: 16 conflict-free LDS.64 + 64 ffma2 -> FMA-bound.
// K in 4 chunks of 64; smem 49.9KB; 2 CTAs/SM.
// ---------------------------------------------------------------------------
#define ATP 65                  // AT row stride (ull)
#define BTP 130                 // BT row stride (ull)
#define AT_U (32 * ATP)
#define BT_U (32 * BTP)

__global__ __launch_bounds__(128, 2)
void gx_gemm_kernel(const float* __restrict__ x, const float* __restrict__ Wx,
                    const float* __restrict__ bx)
{
    extern __shared__ ull smu[];
    ull* sAT = smu;             // [32 kpair][ATP]  (m-indexed)
    ull* sBT = smu + AT_U;      // [32 kpair][BTP]  (n-indexed)

    const int tid  = threadIdx.x;
    const int lane = tid & 31;
    const int w    = tid >> 5;
    const int nbase = blockIdx.x * 128;
    const int mbase = blockIdx.y * 64;

    const int mloc0 = w * 16 + ((lane >> 4) << 3);  // + j (j<8)
    const int nloc0 = lane & 15;                    // + 16*i (i<8)

    // CTA-uniform output decode (128-n tile never straddles a gate)
    const int l   = (nbase >= 768) ? 1 : 0;
    const int rr  = nbase - l * 768;
    const int g3  = rr >> 8;
    const int h0  = (rr & 255) + nloc0;

    float bias[8];
#pragma unroll
    for (int i = 0; i < 8; i++) bias[i] = bx[nbase + nloc0 + 16 * i];

    ull acc[8][8];
#pragma unroll
    for (int j = 0; j < 8; j++)
#pragma unroll
        for (int i = 0; i < 8; i++) acc[j][i] = 0ull;

    for (int kc = 0; kc < 4; kc++) {
        const int kofs = kc * 64;
        __syncthreads();   // previous compute done before smem overwrite

        // --- A chunk: 64m x 64k -> AT[kpair][m] (8 float4 per thread) ---
        {
            float4 v[8];
#pragma unroll
            for (int s = 0; s < 8; s++) {
                int idx = tid + s * 128;
                int m = idx >> 4, k4 = idx & 15;
                v[s] = *reinterpret_cast<const float4*>(
                    x + (((size_t)(mbase + m)) << 8) + kofs + (k4 << 2));
            }
#pragma unroll
            for (int s = 0; s < 8; s++) {
                int idx = tid + s * 128;
                int m = idx >> 4, k4 = idx & 15;
                const ull* p = reinterpret_cast<const ull*>(&v[s]);
                sAT[(2 * k4 + 0) * ATP + m] = p[0];
                sAT[(2 * k4 + 1) * ATP + m] = p[1];
            }
        }
        // --- B chunk: 128n x 64k -> BT[kpair][n] (2 halves of 8 float4) ---
#pragma unroll
        for (int half = 0; half < 2; half++) {
            float4 v[8];
#pragma unroll
            for (int s = 0; s < 8; s++) {
                int idx = tid + s * 128;
                int n = half * 64 + (idx >> 4), k4 = idx & 15;
                v[s] = *reinterpret_cast<const float4*>(
                    Wx + (((size_t)(nbase + n)) << 8) + kofs + (k4 << 2));
            }
#pragma unroll
            for (int s = 0; s < 8; s++) {
                int idx = tid + s * 128;
                int n = half * 64 + (idx >> 4), k4 = idx & 15;
                const ull* p = reinterpret_cast<const ull*>(&v[s]);
                sBT[(2 * k4 + 0) * BTP + n] = p[0];
                sBT[(2 * k4 + 1) * BTP + n] = p[1];
            }
        }
        __syncthreads();

        // --- compute: 32 kpairs, outer product 8m x 8n ---
#pragma unroll 4
        for (int q = 0; q < 32; q++) {
            ull bn[8];
#pragma unroll
            for (int i = 0; i < 8; i++)
                bn[i] = sBT[q * BTP + nloc0 + 16 * i];
#pragma unroll
            for (int j = 0; j < 8; j++) {
                const ull am = sAT[q * ATP + mloc0 + j];
#pragma unroll
                for (int i = 0; i < 8; i++)
                    ffma2(acc[j][i], am, bn[i]);
            }
        }
    }

    // --- epilogue: scatter into g_gx[t][l][g3][b][h], h-coalesced ---
#pragma unroll
    for (int j = 0; j < 8; j++) {
        const int m = mbase + mloc0 + j;
        const int b = m >> 11;
        const int t = m & 2047;
        const size_t rowbase =
            ((((size_t)t * LAY + l) * 3 + g3) * BSZ + b) * HID + h0;
#pragma unroll
        for (int i = 0; i < 8; i++)
            g_gx[rowbase + 16 * i] = hsum2(acc[j][i]) + bias[i];
    }
}

// ---------------------------------------------------------------------------
// Kernel 2: cluster-persistent GRU scan — EXACT R13 config (3.769 ms measured).
// 128 CTAs = 4 groups x 8 batch-chunks(4) x 4-CTA cluster, 256 threads.
// ---------------------------------------------------------------------------
#define SC_THREADS 256
#define PADK    260
#define SW3_F   (2 * 32 * PADK)                  // 16640 floats
#define PART_F  (4 * 192 * 2)                    //  1536 floats per half-plane
#define HBUF_F  (2 * 4 * 256)                    //  2048 floats

__device__ __forceinline__ void st_cluster_v2(uint32_t saddr, int trank, float v0, float v1)
{
    uint32_t ra;
    asm volatile("mapa.shared::cluster.u32 %0, %1, %2;" : "=r"(ra) : "r"(saddr), "r"(trank));
    asm volatile("st.shared::cluster.v2.f32 [%0], {%1, %2};" :: "r"(ra), "f"(v0), "f"(v1) : "memory");
}
__device__ __forceinline__ void cluster_arrive()
{ asm volatile("barrier.cluster.arrive.aligned;" ::: "memory"); }
__device__ __forceinline__ void cluster_wait()
{ asm volatile("barrier.cluster.wait.aligned;" ::: "memory"); }
__device__ __forceinline__ float sig_fast(float x) {
    return __fdividef(1.f, 1.f + __expf(-x));
}
__device__ __forceinline__ float tanh_fast(float x) {
    x = fminf(fmaxf(x, -15.f), 15.f);
    float e = __expf(2.f * x);
    return __fdividef(e - 1.f, e + 1.f);
}

__global__ void __cluster_dims__(4, 1, 1) __launch_bounds__(SC_THREADS, 1)
gru_scan_kernel(const float* __restrict__ Wh, const float* __restrict__ bh,
                float* __restrict__ out)
{
    extern __shared__ float sm[];
    float* sw3   = sm;                  // [64 rows][PADK]  (row2 weights)
    float* partA = sw3 + SW3_F;         // [4 kc][192 rr] float2 (b0,b1)
    float* partB = partA + PART_F;      // [4 kc][192 rr] float2 (b2,b3)
    float* hbuf  = partB + PART_F;      // [2 p][4 b][256 k]
    float* ex_r  = hbuf + HBUF_F;       // [4 b][64]
    float* ex_z  = ex_r + 256;
    float* ex_xn = ex_z + 256;
    float* ex_hn = ex_xn + 256;

    const int tid  = threadIdx.x;
    const int lane = tid & 31;
    const int wid  = tid >> 5;
    const int rg   = wid >> 2;          // row group (96 rows)
    const int kc   = wid & 3;           // k-chunk
    const int k0   = kc << 6;

    const int rank = blockIdx.x & 3;
    const int cg   = blockIdx.x >> 2;
    const int g    = cg >> 3;
    const int c    = cg & 7;
    const int l    = g >> 1;
    const int dir  = g & 1;
    const int b0   = c * 4;

    const int gi = tid >> 6;
    const int li = tid & 63;
    const int hiA = rank * 64 + li;

    const int bbB = tid >> 5;
    const int jjB = tid & 31;
    const int hiB = rank * 64 + jjB * 2;

    const float* WhL = Wh + (size_t)l * 768 * 256;

    const int rrA = rg * 96 + lane * 3;
    ull w0r[32], w1r[32];
    {
        int r0 = rrA + 0, r1 = rrA + 1;
        const ull* p0 = reinterpret_cast<const ull*>(
            WhL + (size_t)((r0 >> 6) * 256 + rank * 64 + (r0 & 63)) * 256 + k0);
        const ull* p1 = reinterpret_cast<const ull*>(
            WhL + (size_t)((r1 >> 6) * 256 + rank * 64 + (r1 & 63)) * 256 + k0);
#pragma unroll
        for (int q = 0; q < 32; q++) { w0r[q] = p0[q]; w1r[q] = p1[q]; }
    }

    for (int i = tid; i < 2 * 32 * 256; i += SC_THREADS) {
        int ri = i >> 8;
        int k  = i & 255;
        int rg_ = ri >> 5;
        int ln  = ri & 31;
        int rr  = rg_ * 96 + ln * 3 + 2;
        sw3[ri * PADK + k] = WhL[(size_t)((rr >> 6) * 256 + rank * 64 + (rr & 63)) * 256 + k];
    }
    for (int i = tid; i < HBUF_F; i += SC_THREADS) hbuf[i] = 0.f;

    const float bhv = (tid < 192) ? bh[l * 768 + gi * 256 + hiA] : 0.f;

    __syncthreads();
    cluster_arrive(); cluster_wait();
    cluster_arrive();

    const uint32_t hbuf_saddr = (uint32_t)__cvta_generic_to_shared(hbuf);
    const size_t gsz = (size_t)BSZ * HID;

    float hpe = 0.f, hpo = 0.f;
    int p = 0;

    for (int step = 0; step < T_LEN; step++) {
        const int t = dir ? (T_LEN - 1 - step) : step;

        float gx0, gx1, gx2, gx3;
        if (tid < 192) {
            const size_t base = ((size_t)t * LAY + l) * 3 * BSZ * HID
                              + (size_t)gi * gsz + (size_t)b0 * HID + hiA;
            gx0 = __ldg(g_gx + base);
            gx1 = __ldg(g_gx + base + HID);
            gx2 = __ldg(g_gx + base + 2 * HID);
            gx3 = __ldg(g_gx + base + 3 * HID);
        }

        cluster_wait();

        ull a00 = 0, a01 = 0, a02 = 0, a03 = 0;
        ull a10 = 0, a11 = 0, a12 = 0, a13 = 0;
        ull a20 = 0, a21 = 0, a22 = 0, a23 = 0;
        {
            const ulonglong2* h0p = reinterpret_cast<const ulonglong2*>(hbuf + ((p * 4 + 0) << 8) + k0);
            const ulonglong2* h1p = reinterpret_cast<const ulonglong2*>(hbuf + ((p * 4 + 1) << 8) + k0);
            const ulonglong2* h2p = reinterpret_cast<const ulonglong2*>(hbuf + ((p * 4 + 2) << 8) + k0);
            const ulonglong2* h3p = reinterpret_cast<const ulonglong2*>(hbuf + ((p * 4 + 3) << 8) + k0);
            const ulonglong2* w3p = reinterpret_cast<const ulonglong2*>(
                sw3 + (rg * 32 + lane) * PADK + k0);

#pragma unroll
            for (int q = 0; q < 16; q++) {
                const ulonglong2 w3 = w3p[q];
                const ulonglong2 hh0 = h0p[q];
                const ulonglong2 hh1 = h1p[q];
                const ulonglong2 hh2 = h2p[q];
                const ulonglong2 hh3 = h3p[q];
                const ull wa0 = w0r[2 * q], wa1 = w0r[2 * q + 1];
                const ull wb0 = w1r[2 * q], wb1 = w1r[2 * q + 1];
                ffma2(a00, wa0, hh0.x); ffma2(a00, wa1, hh0.y);
                ffma2(a01, wa0, hh1.x); ffma2(a01, wa1, hh1.y);
                ffma2(a02, wa0, hh2.x); ffma2(a02, wa1, hh2.y);
                ffma2(a03, wa0, hh3.x); ffma2(a03, wa1, hh3.y);
                ffma2(a10, wb0, hh0.x); ffma2(a10, wb1, hh0.y);
                ffma2(a11, wb0, hh1.x); ffma2(a11, wb1, hh1.y);
                ffma2(a12, wb0, hh2.x); ffma2(a12, wb1, hh2.y);
                ffma2(a13, wb0, hh3.x); ffma2(a13, wb1, hh3.y);
                ffma2(a20, w3.x, hh0.x); ffma2(a20, w3.y, hh0.y);
                ffma2(a21, w3.x, hh1.x); ffma2(a21, w3.y, hh1.y);
                ffma2(a22, w3.x, hh2.x); ffma2(a22, w3.y, hh2.y);
                ffma2(a23, w3.x, hh3.x); ffma2(a23, w3.y, hh3.y);
            }
        }
        {
            float2* pA = reinterpret_cast<float2*>(partA) + kc * 192 + rrA;
            float2* pB = reinterpret_cast<float2*>(partB) + kc * 192 + rrA;
            pA[0] = make_float2(hsum2(a00), hsum2(a01));
            pB[0] = make_float2(hsum2(a02), hsum2(a03));
            pA[1] = make_float2(hsum2(a10), hsum2(a11));
            pB[1] = make_float2(hsum2(a12), hsum2(a13));
            pA[2] = make_float2(hsum2(a20), hsum2(a21));
            pB[2] = make_float2(hsum2(a22), hsum2(a23));
        }
        __syncthreads();

        if (tid < 192) {
            const float2* pA2 = reinterpret_cast<const float2*>(partA);
            const float2* pB2 = reinterpret_cast<const float2*>(partB);
            float2 q0 = pA2[tid], q1 = pA2[192 + tid], q2 = pA2[384 + tid], q3 = pA2[576 + tid];
            const float s0 = (q0.x + q1.x) + (q2.x + q3.x) + bhv;
            const float s1 = (q0.y + q1.y) + (q2.y + q3.y) + bhv;
            q0 = pB2[tid]; q1 = pB2[192 + tid]; q2 = pB2[384 + tid]; q3 = pB2[576 + tid];
            const float s2 = (q0.x + q1.x) + (q2.x + q3.x) + bhv;
            const float s3 = (q0.y + q1.y) + (q2.y + q3.y) + bhv;

            if (gi == 0) {
                ex_r[0 * 64 + li] = sig_fast(gx0 + s0);
                ex_r[1 * 64 + li] = sig_fast(gx1 + s1);
                ex_r[2 * 64 + li] = sig_fast(gx2 + s2);
                ex_r[3 * 64 + li] = sig_fast(gx3 + s3);
            } else if (gi == 1) {
                ex_z[0 * 64 + li] = sig_fast(gx0 + s0);
                ex_z[1 * 64 + li] = sig_fast(gx1 + s1);
                ex_z[2 * 64 + li] = sig_fast(gx2 + s2);
                ex_z[3 * 64 + li] = sig_fast(gx3 + s3);
            } else {
                ex_xn[0 * 64 + li] = gx0;  ex_hn[0 * 64 + li] = s0;
                ex_xn[1 * 64 + li] = gx1;  ex_hn[1 * 64 + li] = s1;
                ex_xn[2 * 64 + li] = gx2;  ex_hn[2 * 64 + li] = s2;
                ex_xn[3 * 64 + li] = gx3;  ex_hn[3 * 64 + li] = s3;
            }
        }
        __syncthreads();

        float hOutE = 0.f, hOutO = 0.f;
        if (tid < 128) {
            const int ei = bbB * 32 + jjB;
            const float2 rr2 = reinterpret_cast<const float2*>(ex_r)[ei];
            const float2 zz2 = reinterpret_cast<const float2*>(ex_z)[ei];
            const float2 xn2 = reinterpret_cast<const float2*>(ex_xn)[ei];
            const float2 hn2 = reinterpret_cast<const float2*>(ex_hn)[ei];

            const float nE = tanh_fast(xn2.x + rr2.x * hn2.x);
            const float nO = tanh_fast(xn2.y + rr2.y * hn2.y);
            hOutE = (1.f - zz2.x) * nE + zz2.x * hpe;
            hOutO = (1.f - zz2.y) * nO + zz2.y * hpo;
            hpe = hOutE; hpo = hOutO;

            const uint32_t la = hbuf_saddr
                + (uint32_t)(((((1 - p) * 4 + bbB) << 8) + hiB) * 4);
            st_cluster_v2(la, 0, hOutE, hOutO);
            st_cluster_v2(la, 1, hOutE, hOutO);
            st_cluster_v2(la, 2, hOutE, hOutO);
            st_cluster_v2(la, 3, hOutE, hOutO);
        }

        cluster_arrive();

        if (tid < 128) {
            float2* po = reinterpret_cast<float2*>(
                out + (size_t)(b0 + bbB) * ((size_t)T_LEN * LAY * 2 * HID)
                    + ((size_t)t * LAY + l) * (2 * HID) + dir * HID + hiB);
            *po = make_float2(hOutE, hOutO);
        }
        p ^= 1;
    }
    cluster_wait();
}

// ---------------------------------------------------------------------------
extern "C" void kernel_launch(void* const* d_in, const int* in_sizes, int n_in,
                              void* d_out, int out_size)
{
    (void)in_sizes; (void)n_in; (void)out_size;
    const float* x  = (const float*)d_in[0];
    const float* Wx = (const float*)d_in[1];
    const float* Wh = (const float*)d_in[2];
    const float* bx = (const float*)d_in[3];
    const float* bh = (const float*)d_in[4];
    float* out = (float*)d_out;

    const int smem1 = (AT_U + BT_U) * 8;                                //  49,920 B
    const int smem2 = (SW3_F + 2 * PART_F + HBUF_F + 4 * 256) * 4;      //  91,136 B

    cudaFuncSetAttribute(gx_gemm_kernel, cudaFuncAttributeMaxDynamicSharedMemorySize, smem1);
    cudaFuncSetAttribute(gru_scan_kernel, cudaFuncAttributeMaxDynamicSharedMemorySize, smem2);

    dim3 grid1(1536 / 128, 65536 / 64);   // 12 x 1024 CTAs, 128 threads each
    gx_gemm_kernel<<<grid1, 128, smem1>>>(x, Wx, bx);

    gru_scan_kernel<<<128, SC_THREADS, smem2>>>(Wh, bh, out);
}